// round 10
// baseline (speedup 1.0000x reference)
#include <cuda_runtime.h>
#include <cuda_bf16.h>
#include <math.h>

// ---------------- problem constants ----------------
#define F_DIM 128
#define IN_DIM 129          // F_DIM + 1 (binary feature)
#define H_DIM 64
#define NEG_SLOPE 0.2f
#define N_MAX 50000
#define E_MAX 800000

// ---------------- scratch (no allocations allowed) ----------------
__device__ __align__(16) float g_xl[N_MAX * H_DIM];
__device__ __align__(16) float g_xr[N_MAX * H_DIM];
__device__ __align__(16) float g_h [N_MAX * H_DIM];
__device__ int   g_deg[N_MAX];
__device__ int   g_rowptr[N_MAX + 1];
__device__ int   g_cursor[N_MAX];
__device__ int   g_adj[E_MAX];
__device__ __align__(16) int g_eidx[2 * E_MAX];
__device__ int   g_is64;
__device__ int   g_bsum[64];
__device__ int   g_boff[64];

// ============================================================
// 0) Edge dtype detection + conversion.
// ============================================================
__global__ void detect_kernel(const int* __restrict__ w, int nwords) {
    if (threadIdx.x == 0 && blockIdx.x == 0) {
        int is64 = 1;
        for (int i = 0; i < 64; i++) {
            int idx = 2 * i + 1;
            if (idx >= nwords) break;
            if (w[idx] != 0) { is64 = 0; break; }
        }
        g_is64 = is64;
    }
}

__global__ void convert_kernel(const void* __restrict__ ei, int total) {
    int e = blockIdx.x * blockDim.x + threadIdx.x;
    if (e < total) {
        g_eidx[e] = g_is64 ? (int)((const long long*)ei)[e]
                           : ((const int*)ei)[e];
    }
}

// ============================================================
// 1) Input projection GEMM: x[N,129] @ [Wl;Wr]^T -> xl[N,64], xr[N,64]
//    K padded 129->130 (stride 130 = 2 mod 32): float2 LDS.64 inner
//    loop is bank-conflict-free. Staging stays scalar (R3-proven).
//    99.8KB smem => 2 CTAs/SM.
// ============================================================
#define KP2 130
#define PROJ_SMEM ((128 + 64) * KP2 * 4)

__global__ __launch_bounds__(256) void proj_kernel(
        const float* __restrict__ xf,
        const float* __restrict__ xb,
        const float* __restrict__ Wl,
        const float* __restrict__ bl,
        const float* __restrict__ Wr,
        const float* __restrict__ br,
        int N) {
    extern __shared__ float sm[];
    float* Ws = sm;               // [128][130]  rows 0..63 = Wl, 64..127 = Wr
    float* xs = sm + 128 * KP2;   // [64][130]

    const int tid = threadIdx.x;
    const int n0 = blockIdx.x * 64;

    // stage weights (scalar LDG), zero-pad col 129
    for (int i = tid; i < 128 * KP2; i += 256) {
        int r = i / KP2, k = i - r * KP2;
        float v = 0.f;
        if (k < IN_DIM) v = (r < 64) ? Wl[r * IN_DIM + k] : Wr[(r - 64) * IN_DIM + k];
        Ws[i] = v;
    }
    // stage x (scalar LDG), col 128 = binary feat, col 129 = 0
    for (int i = tid; i < 64 * KP2; i += 256) {
        int n = i / KP2, k = i - n * KP2;
        int node = n0 + n;
        float v = 0.f;
        if (node < N) {
            if (k < F_DIM)           v = xf[(size_t)node * F_DIM + k];
            else if (k == F_DIM)     v = xb[node];
        }
        xs[i] = v;
    }
    __syncthreads();

    const int tn = tid & 15;   // output group (h = tn + 16*j)
    const int tm = tid >> 4;   // node group   (n = tm + 16*i)

    float acc[4][8];
#pragma unroll
    for (int i = 0; i < 4; i++)
#pragma unroll
        for (int j = 0; j < 8; j++) acc[i][j] = 0.f;

    const float* xbase = xs + tm * KP2;
    const float* wbase = Ws + tn * KP2;

#pragma unroll 2
    for (int k = 0; k < KP2; k += 2) {
        float2 xv[4], wv[8];
#pragma unroll
        for (int i = 0; i < 4; i++)
            xv[i] = *(const float2*)(xbase + i * 16 * KP2 + k);
#pragma unroll
        for (int j = 0; j < 8; j++)
            wv[j] = *(const float2*)(wbase + j * 16 * KP2 + k);
#pragma unroll
        for (int i = 0; i < 4; i++)
#pragma unroll
            for (int j = 0; j < 8; j++) {
                acc[i][j] = fmaf(xv[i].x, wv[j].x, acc[i][j]);
                acc[i][j] = fmaf(xv[i].y, wv[j].y, acc[i][j]);
            }
    }

#pragma unroll
    for (int i = 0; i < 4; i++) {
        int node = n0 + tm + 16 * i;
        if (node >= N) continue;
#pragma unroll
        for (int j = 0; j < 8; j++) {
            int h = tn + 16 * j;
            if (h < H_DIM) {
                g_xl[(size_t)node * H_DIM + h] = acc[i][j] + bl[h];
            } else {
                g_xr[(size_t)node * H_DIM + (h - H_DIM)] = acc[i][j] + br[h - H_DIM];
            }
        }
    }
}

// ============================================================
// 2) CSR build
// ============================================================
__global__ void zero_deg_kernel(int N) {
    int i = blockIdx.x * blockDim.x + threadIdx.x;
    if (i < N) g_deg[i] = 0;
}

__global__ void hist_kernel(int E, int N) {
    int e = blockIdx.x * blockDim.x + threadIdx.x;
    if (e < E) {
        int d = g_eidx[E + e];   // dst
        if ((unsigned)d < (unsigned)N) atomicAdd(&g_deg[d], 1);
    }
}

// multi-block 3-phase scan of g_deg -> g_rowptr/g_cursor
__global__ void scan_block_kernel(int N) {
    __shared__ int s[1024];
    const int b = blockIdx.x, t = threadIdx.x;
    const int idx = b * 1024 + t;
    int v = (idx < N) ? g_deg[idx] : 0;
    s[t] = v;
    __syncthreads();
    for (int off = 1; off < 1024; off <<= 1) {
        int x = (t >= off) ? s[t - off] : 0;
        __syncthreads();
        s[t] += x;
        __syncthreads();
    }
    if (idx < N) g_rowptr[idx + 1] = s[t];   // local inclusive (block offset later)
    if (t == 1023) g_bsum[b] = s[1023];
}

__global__ void scan_tops_kernel(int NB) {
    __shared__ int s[64];
    const int t = threadIdx.x;
    int v = (t < NB) ? g_bsum[t] : 0;
    s[t] = v;
    __syncthreads();
    for (int off = 1; off < 64; off <<= 1) {
        int x = (t >= off) ? s[t - off] : 0;
        __syncthreads();
        s[t] += x;
        __syncthreads();
    }
    if (t < NB) g_boff[t] = s[t] - v;   // exclusive
}

__global__ void scan_fix_kernel(int N) {
    int i = blockIdx.x * blockDim.x + threadIdx.x;
    if (i < N) {
        int r = g_rowptr[i + 1] + g_boff[i >> 10];
        g_rowptr[i + 1] = r;
        g_cursor[i] = r - g_deg[i];
    }
    if (i == 0) g_rowptr[0] = 0;
}

__global__ void scatter_kernel(int E, int N) {
    int e = blockIdx.x * blockDim.x + threadIdx.x;
    if (e < E) {
        int s = g_eidx[e];       // src
        int d = g_eidx[E + e];   // dst
        if ((unsigned)d < (unsigned)N && (unsigned)s < (unsigned)N) {
            int pos = atomicAdd(&g_cursor[d], 1);
            if (pos < E_MAX) g_adj[pos] = s;
        }
    }
}

// ============================================================
// 3) Per-node GATv2 attention + aggregation (VERBATIM from R9).
// ============================================================
__global__ void agg_kernel(const float* __restrict__ att,
                           const float* __restrict__ gbias, int N) {
    const int warp = (blockIdx.x * blockDim.x + threadIdx.x) >> 5;
    const int lane = threadIdx.x & 31;
    if (warp >= N) return;
    const int i = warp;
    const unsigned FULL = 0xffffffffu;

    const float2 xri = *(const float2*)(g_xr + (size_t)i * H_DIM + lane * 2);
    float2 a;  a.x = att[lane * 2];  a.y = att[lane * 2 + 1];
    const float2 xli = *(const float2*)(g_xl + (size_t)i * H_DIM + lane * 2);

    auto partial = [&](float2 xlj) -> float {
        float v0 = xlj.x + xri.x;
        float v1 = xlj.y + xri.y;
        v0 = (v0 > 0.f) ? v0 : NEG_SLOPE * v0;
        v1 = (v1 > 0.f) ? v1 : NEG_SLOPE * v1;
        return fmaf(v0, a.x, v1 * a.y);
    };

    float m;
    {
        float p = partial(xli);
#pragma unroll
        for (int off = 16; off > 0; off >>= 1)
            p += __shfl_xor_sync(FULL, p, off);
        m = p;
    }
    float d = 1.f;
    float2 acc = xli;

    auto update = [&](float sc, float2 xlj) {
        if (sc <= m) {
            float w = __expf(sc - m);
            d += w;
            acc.x = fmaf(w, xlj.x, acc.x);
            acc.y = fmaf(w, xlj.y, acc.y);
        } else {
            float scale = __expf(m - sc);
            d = fmaf(d, scale, 1.f);
            acc.x = fmaf(acc.x, scale, xlj.x);
            acc.y = fmaf(acc.y, scale, xlj.y);
            m = sc;
        }
    };

    const int s = g_rowptr[i], e = g_rowptr[i + 1];
    for (int b = s; b < e; b += 32) {
        int myj = (b + lane < e) ? g_adj[b + lane] : 0;
        int cnt = min(32, e - b);
        int k = 0;
        for (; k + 1 < cnt; k += 2) {
            int j0 = __shfl_sync(FULL, myj, k);
            int j1 = __shfl_sync(FULL, myj, k + 1);
            float2 x0 = *(const float2*)(g_xl + (size_t)j0 * H_DIM + lane * 2);
            float2 x1 = *(const float2*)(g_xl + (size_t)j1 * H_DIM + lane * 2);
            float p0 = partial(x0);
            float p1 = partial(x1);
#pragma unroll
            for (int off = 16; off > 0; off >>= 1) {
                p0 += __shfl_xor_sync(FULL, p0, off);
                p1 += __shfl_xor_sync(FULL, p1, off);
            }
            update(p0, x0);
            update(p1, x1);
        }
        if (k < cnt) {
            int j0 = __shfl_sync(FULL, myj, k);
            float2 x0 = *(const float2*)(g_xl + (size_t)j0 * H_DIM + lane * 2);
            float p0 = partial(x0);
#pragma unroll
            for (int off = 16; off > 0; off >>= 1)
                p0 += __shfl_xor_sync(FULL, p0, off);
            update(p0, x0);
        }
    }

    const float inv = 1.f / d;
    float gb0 = gbias[lane * 2], gb1 = gbias[lane * 2 + 1];
    float o0 = fmaf(acc.x, inv, gb0);
    float o1 = fmaf(acc.y, inv, gb1);
    o0 = (o0 > 0.f) ? o0 : (__expf(o0) - 1.f);
    o1 = (o1 > 0.f) ? o1 : (__expf(o1) - 1.f);
    float2 r; r.x = o0; r.y = o1;
    *(float2*)(g_h + (size_t)i * H_DIM + lane * 2) = r;
}

// ============================================================
// 4) Output GEMM (VERBATIM from the passing R3/R9 kernel).
// ============================================================
__global__ void outgemm_kernel(const float* __restrict__ Wo,
                               const float* __restrict__ bo,
                               float* __restrict__ out, int N) {
    __shared__ float Ws[128 * 65];   // padded stride 65 (odd)
    __shared__ float hs[32 * 65];

    const int tid = threadIdx.x;
    const int n0 = blockIdx.x * 32;

    for (int i = tid; i < 128 * 64; i += 256) {
        int f = i >> 6, k = i & 63;
        Ws[f * 65 + k] = Wo[i];
    }
    for (int i = tid; i < 32 * 64; i += 256) {
        int n = i >> 6, k = i & 63;
        int node = n0 + n;
        hs[n * 65 + k] = (node < N) ? g_h[(size_t)node * H_DIM + k] : 0.f;
    }
    __syncthreads();

    const int tn = tid & 15;   // f = tn + 16*j
    const int tm = tid >> 4;   // n = tm + 16*i

    float acc[2][8];
#pragma unroll
    for (int i = 0; i < 2; i++)
#pragma unroll
        for (int j = 0; j < 8; j++) acc[i][j] = 0.f;

#pragma unroll 4
    for (int k = 0; k < H_DIM; k++) {
        float xv[2], wv[8];
#pragma unroll
        for (int i = 0; i < 2; i++) xv[i] = hs[(tm + 16 * i) * 65 + k];
#pragma unroll
        for (int j = 0; j < 8; j++) wv[j] = Ws[(tn + 16 * j) * 65 + k];
#pragma unroll
        for (int i = 0; i < 2; i++)
#pragma unroll
            for (int j = 0; j < 8; j++) acc[i][j] = fmaf(xv[i], wv[j], acc[i][j]);
    }

#pragma unroll
    for (int i = 0; i < 2; i++) {
        int node = n0 + tm + 16 * i;
        if (node >= N) continue;
#pragma unroll
        for (int j = 0; j < 8; j++) {
            int f = tn + 16 * j;
            out[(size_t)node * F_DIM + f] = acc[i][j] + bo[f];
        }
    }
}

// ============================================================
// 5) dispersion tail: softplus
// ============================================================
__global__ void disp_kernel(const float* __restrict__ disp, float* __restrict__ out) {
    int t = threadIdx.x;
    if (t < F_DIM) {
        float x = disp[t];
        out[t] = fmaxf(x, 0.f) + log1pf(__expf(-fabsf(x)));
    }
}

// ============================================================
extern "C" void kernel_launch(void* const* d_in, const int* in_sizes, int n_in,
                              void* d_out, int out_size) {
    const float*     xf   = (const float*)d_in[0];
    const float*     xb   = (const float*)d_in[1];
    const void*      ei   = d_in[2];
    const float*     Wl   = (const float*)d_in[3];
    const float*     bl   = (const float*)d_in[4];
    const float*     Wr   = (const float*)d_in[5];
    const float*     br   = (const float*)d_in[6];
    const float*     att  = (const float*)d_in[7];
    const float*     gb   = (const float*)d_in[8];
    const float*     Wo   = (const float*)d_in[9];
    const float*     bo   = (const float*)d_in[10];
    const float*     disp = (const float*)d_in[11];

    const int N = in_sizes[0] / F_DIM;
    const int E = in_sizes[2] / 2;
    const int NB = (N + 1023) / 1024;
    float* out = (float*)d_out;

    cudaFuncSetAttribute(proj_kernel,
                         cudaFuncAttributeMaxDynamicSharedMemorySize, PROJ_SMEM);

    detect_kernel<<<1, 32>>>((const int*)ei, 2 * E);
    convert_kernel<<<(2 * E + 255) / 256, 256>>>(ei, 2 * E);
    zero_deg_kernel<<<(N + 255) / 256, 256>>>(N);
    proj_kernel<<<(N + 63) / 64, 256, PROJ_SMEM>>>(xf, xb, Wl, bl, Wr, br, N);
    hist_kernel<<<(E + 255) / 256, 256>>>(E, N);
    scan_block_kernel<<<NB, 1024>>>(N);
    scan_tops_kernel<<<1, 64>>>(NB);
    scan_fix_kernel<<<(N + 255) / 256, 256>>>(N);
    scatter_kernel<<<(E + 255) / 256, 256>>>(E, N);
    agg_kernel<<<(N + 7) / 8, 256>>>(att, gb, N);
    outgemm_kernel<<<(N + 31) / 32, 256>>>(Wo, bo, out, N);
    disp_kernel<<<1, 128>>>(disp, out + (size_t)N * F_DIM);
}

// round 11
// speedup vs baseline: 1.1394x; 1.1394x over previous
#include <cuda_runtime.h>
#include <cuda_bf16.h>
#include <math.h>

// ---------------- problem constants ----------------
#define F_DIM 128
#define IN_DIM 129          // F_DIM + 1 (binary feature)
#define H_DIM 64
#define NEG_SLOPE 0.2f
#define N_MAX 50000
#define E_MAX 800000

// ---------------- scratch (no allocations allowed) ----------------
__device__ __align__(16) float g_xl[N_MAX * H_DIM];
__device__ __align__(16) float g_xr[N_MAX * H_DIM];
__device__ __align__(16) float g_h [N_MAX * H_DIM];
__device__ int   g_deg[N_MAX];
__device__ int   g_rowptr[N_MAX + 1];
__device__ int   g_cursor[N_MAX];
__device__ int   g_adj[E_MAX];
__device__ __align__(16) int g_eidx[2 * E_MAX];
__device__ int   g_is64;
__device__ int   g_bsum[64];
__device__ int   g_boff[64];

// ============================================================
// 0) Edge dtype detection + conversion.
// ============================================================
__global__ void detect_kernel(const int* __restrict__ w, int nwords) {
    if (threadIdx.x == 0 && blockIdx.x == 0) {
        int is64 = 1;
        for (int i = 0; i < 64; i++) {
            int idx = 2 * i + 1;
            if (idx >= nwords) break;
            if (w[idx] != 0) { is64 = 0; break; }
        }
        g_is64 = is64;
    }
}

__global__ void convert_kernel(const void* __restrict__ ei, int total) {
    int e = blockIdx.x * blockDim.x + threadIdx.x;
    if (e < total) {
        g_eidx[e] = g_is64 ? (int)((const long long*)ei)[e]
                           : ((const int*)ei)[e];
    }
}

// ============================================================
// 1) Input projection GEMM: x[N,129] @ [Wl;Wr]^T -> xl[N,64], xr[N,64]
//    R3 layout (stride 129, conflict-free, scalar staging) + explicit
//    2-deep register double-buffer: each 12-LDS batch is hidden under
//    the previous k's independent 32-FFMA block.
// ============================================================
#define PROJ_SMEM ((128 * IN_DIM + 64 * IN_DIM) * 4)

__global__ __launch_bounds__(256) void proj_kernel(
        const float* __restrict__ xf,
        const float* __restrict__ xb,
        const float* __restrict__ Wl,
        const float* __restrict__ bl,
        const float* __restrict__ Wr,
        const float* __restrict__ br,
        int N) {
    extern __shared__ float sm[];
    float* Ws = sm;                  // [128][129]  rows 0..63 = Wl, 64..127 = Wr
    float* xs = sm + 128 * IN_DIM;   // [64][129]

    const int tid = threadIdx.x;
    const int n0 = blockIdx.x * 64;

    for (int i = tid; i < 64 * IN_DIM; i += 256) Ws[i] = Wl[i];
    for (int i = tid; i < 64 * IN_DIM; i += 256) Ws[64 * IN_DIM + i] = Wr[i];
    for (int i = tid; i < 64 * IN_DIM; i += 256) {
        int n = i / IN_DIM, k = i - n * IN_DIM;
        int node = n0 + n;
        float v = 0.f;
        if (node < N) v = (k < F_DIM) ? xf[(size_t)node * F_DIM + k] : xb[node];
        xs[i] = v;
    }
    __syncthreads();

    const int tn = tid & 15;   // output group (h = tn + 16*j)
    const int tm = tid >> 4;   // node group   (n = tm + 16*i)

    float acc[4][8];
#pragma unroll
    for (int i = 0; i < 4; i++)
#pragma unroll
        for (int j = 0; j < 8; j++) acc[i][j] = 0.f;

    const float* xbase = xs + tm * IN_DIM;
    const float* wbase = Ws + tn * IN_DIM;

    float xv0[4], wv0[8], xv1[4], wv1[8];

#define LOADX(buf, kk)                                        \
    {                                                         \
        _Pragma("unroll")                                     \
        for (int i = 0; i < 4; i++)                           \
            buf[i] = xbase[i * 16 * IN_DIM + (kk)];           \
    }
#define LOADW(buf, kk)                                        \
    {                                                         \
        _Pragma("unroll")                                     \
        for (int j = 0; j < 8; j++)                           \
            buf[j] = wbase[j * 16 * IN_DIM + (kk)];           \
    }
#define FFMAS(xb_, wb_)                                       \
    {                                                         \
        _Pragma("unroll")                                     \
        for (int i = 0; i < 4; i++)                           \
            _Pragma("unroll")                                 \
            for (int j = 0; j < 8; j++)                       \
                acc[i][j] = fmaf(xb_[i], wb_[j], acc[i][j]);  \
    }

    LOADX(xv0, 0);
    LOADW(wv0, 0);
#pragma unroll 2
    for (int k = 0; k + 2 < IN_DIM; k += 2) {
        LOADX(xv1, k + 1);
        LOADW(wv1, k + 1);
        FFMAS(xv0, wv0);
        LOADX(xv0, k + 2);
        LOADW(wv0, k + 2);
        FFMAS(xv1, wv1);
    }
    // epilogue: K=129 odd — loop exits at k=128, buf0 holds k=128
    FFMAS(xv0, wv0);

#undef LOADX
#undef LOADW
#undef FFMAS

#pragma unroll
    for (int i = 0; i < 4; i++) {
        int node = n0 + tm + 16 * i;
        if (node >= N) continue;
#pragma unroll
        for (int j = 0; j < 8; j++) {
            int h = tn + 16 * j;
            if (h < H_DIM) {
                g_xl[(size_t)node * H_DIM + h] = acc[i][j] + bl[h];
            } else {
                g_xr[(size_t)node * H_DIM + (h - H_DIM)] = acc[i][j] + br[h - H_DIM];
            }
        }
    }
}

// ============================================================
// 2) CSR build
// ============================================================
__global__ void zero_deg_kernel(int N) {
    int i = blockIdx.x * blockDim.x + threadIdx.x;
    if (i < N) g_deg[i] = 0;
}

__global__ void hist_kernel(int E, int N) {
    int e = blockIdx.x * blockDim.x + threadIdx.x;
    if (e < E) {
        int d = g_eidx[E + e];   // dst
        if ((unsigned)d < (unsigned)N) atomicAdd(&g_deg[d], 1);
    }
}

__global__ void scan_block_kernel(int N) {
    __shared__ int s[1024];
    const int b = blockIdx.x, t = threadIdx.x;
    const int idx = b * 1024 + t;
    int v = (idx < N) ? g_deg[idx] : 0;
    s[t] = v;
    __syncthreads();
    for (int off = 1; off < 1024; off <<= 1) {
        int x = (t >= off) ? s[t - off] : 0;
        __syncthreads();
        s[t] += x;
        __syncthreads();
    }
    if (idx < N) g_rowptr[idx + 1] = s[t];
    if (t == 1023) g_bsum[b] = s[1023];
}

__global__ void scan_tops_kernel(int NB) {
    __shared__ int s[64];
    const int t = threadIdx.x;
    int v = (t < NB) ? g_bsum[t] : 0;
    s[t] = v;
    __syncthreads();
    for (int off = 1; off < 64; off <<= 1) {
        int x = (t >= off) ? s[t - off] : 0;
        __syncthreads();
        s[t] += x;
        __syncthreads();
    }
    if (t < NB) g_boff[t] = s[t] - v;
}

__global__ void scan_fix_kernel(int N) {
    int i = blockIdx.x * blockDim.x + threadIdx.x;
    if (i < N) {
        int r = g_rowptr[i + 1] + g_boff[i >> 10];
        g_rowptr[i + 1] = r;
        g_cursor[i] = r - g_deg[i];
    }
    if (i == 0) g_rowptr[0] = 0;
}

__global__ void scatter_kernel(int E, int N) {
    int e = blockIdx.x * blockDim.x + threadIdx.x;
    if (e < E) {
        int s = g_eidx[e];
        int d = g_eidx[E + e];
        if ((unsigned)d < (unsigned)N && (unsigned)s < (unsigned)N) {
            int pos = atomicAdd(&g_cursor[d], 1);
            if (pos < E_MAX) g_adj[pos] = s;
        }
    }
}

// ============================================================
// 3) Per-node GATv2 attention + aggregation (VERBATIM from R9).
// ============================================================
__global__ void agg_kernel(const float* __restrict__ att,
                           const float* __restrict__ gbias, int N) {
    const int warp = (blockIdx.x * blockDim.x + threadIdx.x) >> 5;
    const int lane = threadIdx.x & 31;
    if (warp >= N) return;
    const int i = warp;
    const unsigned FULL = 0xffffffffu;

    const float2 xri = *(const float2*)(g_xr + (size_t)i * H_DIM + lane * 2);
    float2 a;  a.x = att[lane * 2];  a.y = att[lane * 2 + 1];
    const float2 xli = *(const float2*)(g_xl + (size_t)i * H_DIM + lane * 2);

    auto partial = [&](float2 xlj) -> float {
        float v0 = xlj.x + xri.x;
        float v1 = xlj.y + xri.y;
        v0 = (v0 > 0.f) ? v0 : NEG_SLOPE * v0;
        v1 = (v1 > 0.f) ? v1 : NEG_SLOPE * v1;
        return fmaf(v0, a.x, v1 * a.y);
    };

    float m;
    {
        float p = partial(xli);
#pragma unroll
        for (int off = 16; off > 0; off >>= 1)
            p += __shfl_xor_sync(FULL, p, off);
        m = p;
    }
    float d = 1.f;
    float2 acc = xli;

    auto update = [&](float sc, float2 xlj) {
        if (sc <= m) {
            float w = __expf(sc - m);
            d += w;
            acc.x = fmaf(w, xlj.x, acc.x);
            acc.y = fmaf(w, xlj.y, acc.y);
        } else {
            float scale = __expf(m - sc);
            d = fmaf(d, scale, 1.f);
            acc.x = fmaf(acc.x, scale, xlj.x);
            acc.y = fmaf(acc.y, scale, xlj.y);
            m = sc;
        }
    };

    const int s = g_rowptr[i], e = g_rowptr[i + 1];
    for (int b = s; b < e; b += 32) {
        int myj = (b + lane < e) ? g_adj[b + lane] : 0;
        int cnt = min(32, e - b);
        int k = 0;
        for (; k + 1 < cnt; k += 2) {
            int j0 = __shfl_sync(FULL, myj, k);
            int j1 = __shfl_sync(FULL, myj, k + 1);
            float2 x0 = *(const float2*)(g_xl + (size_t)j0 * H_DIM + lane * 2);
            float2 x1 = *(const float2*)(g_xl + (size_t)j1 * H_DIM + lane * 2);
            float p0 = partial(x0);
            float p1 = partial(x1);
#pragma unroll
            for (int off = 16; off > 0; off >>= 1) {
                p0 += __shfl_xor_sync(FULL, p0, off);
                p1 += __shfl_xor_sync(FULL, p1, off);
            }
            update(p0, x0);
            update(p1, x1);
        }
        if (k < cnt) {
            int j0 = __shfl_sync(FULL, myj, k);
            float2 x0 = *(const float2*)(g_xl + (size_t)j0 * H_DIM + lane * 2);
            float p0 = partial(x0);
#pragma unroll
            for (int off = 16; off > 0; off >>= 1)
                p0 += __shfl_xor_sync(FULL, p0, off);
            update(p0, x0);
        }
    }

    const float inv = 1.f / d;
    float gb0 = gbias[lane * 2], gb1 = gbias[lane * 2 + 1];
    float o0 = fmaf(acc.x, inv, gb0);
    float o1 = fmaf(acc.y, inv, gb1);
    o0 = (o0 > 0.f) ? o0 : (__expf(o0) - 1.f);
    o1 = (o1 > 0.f) ? o1 : (__expf(o1) - 1.f);
    float2 r; r.x = o0; r.y = o1;
    *(float2*)(g_h + (size_t)i * H_DIM + lane * 2) = r;
}

// ============================================================
// 4) Output GEMM (VERBATIM from the passing R3/R9 kernel).
// ============================================================
__global__ void outgemm_kernel(const float* __restrict__ Wo,
                               const float* __restrict__ bo,
                               float* __restrict__ out, int N) {
    __shared__ float Ws[128 * 65];   // padded stride 65 (odd)
    __shared__ float hs[32 * 65];

    const int tid = threadIdx.x;
    const int n0 = blockIdx.x * 32;

    for (int i = tid; i < 128 * 64; i += 256) {
        int f = i >> 6, k = i & 63;
        Ws[f * 65 + k] = Wo[i];
    }
    for (int i = tid; i < 32 * 64; i += 256) {
        int n = i >> 6, k = i & 63;
        int node = n0 + n;
        hs[n * 65 + k] = (node < N) ? g_h[(size_t)node * H_DIM + k] : 0.f;
    }
    __syncthreads();

    const int tn = tid & 15;   // f = tn + 16*j
    const int tm = tid >> 4;   // n = tm + 16*i

    float acc[2][8];
#pragma unroll
    for (int i = 0; i < 2; i++)
#pragma unroll
        for (int j = 0; j < 8; j++) acc[i][j] = 0.f;

#pragma unroll 4
    for (int k = 0; k < H_DIM; k++) {
        float xv[2], wv[8];
#pragma unroll
        for (int i = 0; i < 2; i++) xv[i] = hs[(tm + 16 * i) * 65 + k];
#pragma unroll
        for (int j = 0; j < 8; j++) wv[j] = Ws[(tn + 16 * j) * 65 + k];
#pragma unroll
        for (int i = 0; i < 2; i++)
#pragma unroll
            for (int j = 0; j < 8; j++) acc[i][j] = fmaf(xv[i], wv[j], acc[i][j]);
    }

#pragma unroll
    for (int i = 0; i < 2; i++) {
        int node = n0 + tm + 16 * i;
        if (node >= N) continue;
#pragma unroll
        for (int j = 0; j < 8; j++) {
            int f = tn + 16 * j;
            out[(size_t)node * F_DIM + f] = acc[i][j] + bo[f];
        }
    }
}

// ============================================================
// 5) dispersion tail: softplus
// ============================================================
__global__ void disp_kernel(const float* __restrict__ disp, float* __restrict__ out) {
    int t = threadIdx.x;
    if (t < F_DIM) {
        float x = disp[t];
        out[t] = fmaxf(x, 0.f) + log1pf(__expf(-fabsf(x)));
    }
}

// ============================================================
extern "C" void kernel_launch(void* const* d_in, const int* in_sizes, int n_in,
                              void* d_out, int out_size) {
    const float*     xf   = (const float*)d_in[0];
    const float*     xb   = (const float*)d_in[1];
    const void*      ei   = d_in[2];
    const float*     Wl   = (const float*)d_in[3];
    const float*     bl   = (const float*)d_in[4];
    const float*     Wr   = (const float*)d_in[5];
    const float*     br   = (const float*)d_in[6];
    const float*     att  = (const float*)d_in[7];
    const float*     gb   = (const float*)d_in[8];
    const float*     Wo   = (const float*)d_in[9];
    const float*     bo   = (const float*)d_in[10];
    const float*     disp = (const float*)d_in[11];

    const int N = in_sizes[0] / F_DIM;
    const int E = in_sizes[2] / 2;
    const int NB = (N + 1023) / 1024;
    float* out = (float*)d_out;

    cudaFuncSetAttribute(proj_kernel,
                         cudaFuncAttributeMaxDynamicSharedMemorySize, PROJ_SMEM);

    detect_kernel<<<1, 32>>>((const int*)ei, 2 * E);
    convert_kernel<<<(2 * E + 255) / 256, 256>>>(ei, 2 * E);
    zero_deg_kernel<<<(N + 255) / 256, 256>>>(N);
    proj_kernel<<<(N + 63) / 64, 256, PROJ_SMEM>>>(xf, xb, Wl, bl, Wr, br, N);
    hist_kernel<<<(E + 255) / 256, 256>>>(E, N);
    scan_block_kernel<<<NB, 1024>>>(N);
    scan_tops_kernel<<<1, 64>>>(NB);
    scan_fix_kernel<<<(N + 255) / 256, 256>>>(N);
    scatter_kernel<<<(E + 255) / 256, 256>>>(E, N);
    agg_kernel<<<(N + 7) / 8, 256>>>(att, gb, N);
    outgemm_kernel<<<(N + 31) / 32, 256>>>(Wo, bo, out, N);
    disp_kernel<<<1, 128>>>(disp, out + (size_t)N * F_DIM);
}